// round 16
// baseline (speedup 1.0000x reference)
#include <cuda_runtime.h>
#include <cstdint>

#define C_       256
#define NBOX_    1024
#define THREADS_ 512
#define MAXDY_   14
#define SMEMX_   (MAXDY_ * 7 * C_ * 4)   // 100352 bytes: X[item][64] ulonglong2

typedef unsigned long long u64;

__device__ __forceinline__ u64 fma2(u64 a, u64 b, u64 c) {
    u64 d; asm("fma.rn.f32x2 %0,%1,%2,%3;" : "=l"(d) : "l"(a), "l"(b), "l"(c)); return d;
}
__device__ __forceinline__ u64 mul2(u64 a, u64 b) {
    u64 d; asm("mul.rn.f32x2 %0,%1,%2;" : "=l"(d) : "l"(a), "l"(b)); return d;
}
__device__ __forceinline__ u64 bcast2(float w) {
    return (u64)__float_as_uint(w) * 0x100000001ULL;
}
__device__ __forceinline__ u64 bcastf(float w) {
    u64 d; asm("mov.b64 %0,{%1,%1};" : "=l"(d) : "f"(w)); return d;
}
__device__ __forceinline__ void stcs64(void* p, u64 v) {
    asm volatile("st.global.cs.b64 [%0],%1;" :: "l"(p), "l"(v) : "memory");
}

__global__ __launch_bounds__(THREADS_, 2) void roialign_kernel(
    const float* __restrict__ feat0,
    const float* __restrict__ feat1,
    const float* __restrict__ rois,
    float* __restrict__ out)
{
    extern __shared__ ulonglong2 sX2[];      // [dy*7][64]
    __shared__ int   s_xo0[7], s_xo1[7];     // x corner byte offsets
    __shared__ u64   s_ax[7], s_bx[7];       // packed x weights (vx folded)
    __shared__ int   s_yrow[MAXDY_];         // distinct row byte offsets
    __shared__ int   s_i0[7], s_i1[7];
    __shared__ float s_wyA[7], s_wyB[7];
    __shared__ int4  s_cd[52];               // {offA_u64, offB_u64, wAbits, wBbits}
    __shared__ int   s_dy;

    int n = blockIdx.x;
    int t = threadIdx.x;

    const float* roi = rois + (size_t)n * 5;
    float y1 = roi[0], x1 = roi[1], y2 = roi[2], x2 = roi[3];
    bool L = ((y2 - y1) > 48.0f) || ((x2 - x1) > 48.0f);
    int H = L ? 128 : 256;
    float Hm1 = (float)(H - 1);
    int b = n >> 9;
    const float inv = 1.0f / 1024.0f;

    // ---- x setup: threads 0..6 ----
    if (t < 7) {
        float x1n = x1 * inv, x2n = x2 * inv;
        float xs = (x1n + (float)t * (1.0f / 6.0f) * (x2n - x1n)) * Hm1;
        float vx = (xs >= 0.0f && xs <= Hm1) ? 1.0f : 0.0f;
        float xf = floorf(xs);
        float wx = xs - xf;
        int x0 = (int)fminf(fmaxf(xf, 0.0f), Hm1);
        int xp = min(x0 + 1, H - 1);
        s_xo0[t] = x0 * (C_ * 4);
        s_xo1[t] = xp * (C_ * 4);
        s_ax[t] = bcast2((1.0f - wx) * vx);
        s_bx[t] = bcast2(wx * vx);
    }

    // ---- y setup: one thread in a different warp ----
    if (t == 32) {
        float y1n = y1 * inv, y2n = y2 * inv;
        int ylist[MAXDY_];
        int dy = 0;
        #pragma unroll
        for (int r = 0; r < 7; r++) {
            float ys = (y1n + (float)r * (1.0f / 6.0f) * (y2n - y1n)) * Hm1;
            float vy = (ys >= 0.0f && ys <= Hm1) ? 1.0f : 0.0f;
            float yf = floorf(ys);
            float wy = ys - yf;
            int y0 = (int)fminf(fmaxf(yf, 0.0f), Hm1);
            int yp = min(y0 + 1, H - 1);

            int i0;
            if (dy > 0 && y0 == ylist[dy - 1])      i0 = dy - 1;
            else if (dy > 1 && y0 == ylist[dy - 2]) i0 = dy - 2;
            else { ylist[dy] = y0; i0 = dy; dy++; }

            int i1;
            if (yp == ylist[dy - 1]) i1 = dy - 1;
            else { ylist[dy] = yp; i1 = dy; dy++; }

            s_i0[r] = i0;
            s_i1[r] = i1;
            s_wyA[r] = (1.0f - wy) * vy;
            s_wyB[r] = wy * vy;
        }
        s_dy = dy;
        for (int j = 0; j < dy; j++)
            s_yrow[j] = ((b * H + ylist[j]) * H) * (C_ * 4);
    }
    __syncthreads();

    // ---- descriptor table for phase 2 (threads 0..51) ----
    if (t < 52) {
        int4 d;
        if (t < 49) {
            int r = (t * 9363) >> 16;       // t / 7
            int c = t - r * 7;
            d.x = (s_i0[r] * 7 + c) * 128;  // u64-unit offset of pixel
            d.y = (s_i1[r] * 7 + c) * 128;
            d.z = __float_as_int(s_wyA[r]);
            d.w = __float_as_int(s_wyB[r]);
        } else {
            d.x = 0; d.y = 0; d.z = 0; d.w = 0;
        }
        s_cd[t] = d;
    }

    // ---- phase 1: x-interpolate distinct rows -> smem ----
    {
        int cg   = t & 63;        // float4 group
        int lane = t >> 6;        // 0..7
        const char* fb = (const char*)(L ? feat1 : feat0) + cg * 16;
        int nitem = s_dy * 7;

        #pragma unroll 2
        for (int item = lane; item < nitem; item += 8) {
            int j = (item * 9363) >> 16;     // item / 7  (item < 98)
            int c = item - j * 7;
            const char* rb = fb + s_yrow[j];
            ulonglong2 p0 = __ldg((const ulonglong2*)(rb + s_xo0[c]));
            ulonglong2 p1 = __ldg((const ulonglong2*)(rb + s_xo1[c]));
            u64 ax = s_ax[c], bx = s_bx[c];
            ulonglong2 X;
            X.x = fma2(p1.x, bx, mul2(p0.x, ax));
            X.y = fma2(p1.y, bx, mul2(p0.y, ax));
            sX2[item * 64 + cg] = X;
        }
    }
    __syncthreads();

    // ---- phase 2: y-blend from smem, store ----
    {
        int tcg  = t & 127;      // u64 channel pair
        int lane = t >> 7;       // 0..3
        const u64* sXu = (const u64*)sX2;
        char* ob = (char*)out + (size_t)n * 49 * 1024 + tcg * 8;

        #pragma unroll
        for (int k = 0; k < 13; k++) {
            int cell = lane + 4 * k;
            int4 d = s_cd[cell];
            u64 Xa = sXu[d.x + tcg];
            u64 Xb = sXu[d.y + tcg];
            u64 o = fma2(Xb, bcastf(__int_as_float(d.w)),
                         mul2(Xa, bcastf(__int_as_float(d.z))));
            if (cell < 49)
                stcs64(ob + cell * 1024, o);
        }
    }
}

extern "C" void kernel_launch(void* const* d_in, const int* in_sizes, int n_in,
                              void* d_out, int out_size)
{
    const float* feat0 = (const float*)d_in[0];
    const float* feat1 = (const float*)d_in[1];
    const float* rois  = (const float*)d_in[2];
    float* out = (float*)d_out;

    cudaFuncSetAttribute(roialign_kernel,
                         cudaFuncAttributeMaxDynamicSharedMemorySize, SMEMX_);
    roialign_kernel<<<NBOX_, THREADS_, SMEMX_>>>(feat0, feat1, rois, out);
}

// round 17
// speedup vs baseline: 2.6125x; 2.6125x over previous
#include <cuda_runtime.h>
#include <cstdint>

#define B_     2
#define R_     512
#define C_     256
#define H0_    256
#define H1_    128
#define NBOX_  (B_ * R_)            // 1024
#define NCELLB_ 49
#define NPAD_  56                   // 8 lanes x 7 iterations
#define CG_    (C_ / 4)             // 64 float4 groups per pixel
#define THREADS_ 512                // 64 cgroups x 8 cell-lanes

typedef unsigned long long u64;

struct Desc {                // 48 bytes
    int4 o;                  // byte offsets of 4 corners
    ulonglong2 wA;           // packed f32x2: {w00,w00}, {w01,w01}
    ulonglong2 wB;           // packed f32x2: {w10,w10}, {w11,w11}
};

__device__ __forceinline__ u64 fma2(u64 a, u64 b, u64 c) {
    u64 d;
    asm("fma.rn.f32x2 %0, %1, %2, %3;" : "=l"(d) : "l"(a), "l"(b), "l"(c));
    return d;
}
__device__ __forceinline__ u64 mul2(u64 a, u64 b) {
    u64 d;
    asm("mul.rn.f32x2 %0, %1, %2;" : "=l"(d) : "l"(a), "l"(b));
    return d;
}
__device__ __forceinline__ u64 bcast2(float w) {
    return (u64)__float_as_uint(w) * 0x100000001ULL;
}
// 128-bit non-coherent load with L1 evict-last policy (keep reused corner lines)
__device__ __forceinline__ ulonglong2 ldg_el(const void* p) {
    ulonglong2 v;
    asm volatile("ld.global.nc.L1::evict_last.v2.u64 {%0,%1}, [%2];"
                 : "=l"(v.x), "=l"(v.y) : "l"(p));
    return v;
}

__global__ __launch_bounds__(THREADS_, 4) void roialign_kernel(
    const float* __restrict__ feat0,
    const float* __restrict__ feat1,
    const float* __restrict__ rois,
    float* __restrict__ out)
{
    __shared__ Desc cd[NPAD_];
    __shared__ int s_lvl;

    int n = blockIdx.x;
    int t = threadIdx.x;

    if (t < NPAD_) {
        Desc d;
        d.o = make_int4(0, 0, 0, 0);
        d.wA.x = 0; d.wA.y = 0; d.wB.x = 0; d.wB.y = 0;
        if (t < NCELLB_) {
            const float* roi = rois + (size_t)n * 5;
            float y1 = roi[0], x1 = roi[1], y2 = roi[2], x2 = roi[3];
            bool lvl = ((y2 - y1) > 48.0f) || ((x2 - x1) > 48.0f);
            if (t == 0) s_lvl = lvl ? 1 : 0;
            int H = lvl ? H1_ : H0_;
            float Hm1 = (float)(H - 1);
            int b = n >> 9;

            const float inv = 1.0f / 1024.0f;
            float y1n = y1 * inv, x1n = x1 * inv, y2n = y2 * inv, x2n = x2 * inv;

            int py = t / 7;
            int px = t - py * 7;
            float ry = (float)py * (1.0f / 6.0f);
            float rx = (float)px * (1.0f / 6.0f);
            float ys = (y1n + ry * (y2n - y1n)) * Hm1;
            float xs = (x1n + rx * (x2n - x1n)) * Hm1;

            float validf = ((ys >= 0.0f) && (ys <= Hm1) && (xs >= 0.0f) && (xs <= Hm1))
                           ? 1.0f : 0.0f;

            float y0f = floorf(ys);
            float x0f = floorf(xs);
            float wy = ys - y0f;
            float wx = xs - x0f;
            int y0 = (int)fminf(fmaxf(y0f, 0.0f), Hm1);
            int x0 = (int)fminf(fmaxf(x0f, 0.0f), Hm1);
            int yp = min(y0 + 1, H - 1);
            int xp = min(x0 + 1, H - 1);

            int rowB = H * (C_ * 4);
            int baseB  = (b * H + y0) * rowB;
            int basePB = (b * H + yp) * rowB;

            d.o.x = baseB  + x0 * (C_ * 4);
            d.o.y = baseB  + xp * (C_ * 4);
            d.o.z = basePB + x0 * (C_ * 4);
            d.o.w = basePB + xp * (C_ * 4);

            float omwx = 1.0f - wx;
            float omwy = 1.0f - wy;
            d.wA.x = bcast2(omwx * omwy * validf);
            d.wA.y = bcast2(wx   * omwy * validf);
            d.wB.x = bcast2(omwx * wy   * validf);
            d.wB.y = bcast2(wx   * wy   * validf);
        }
        cd[t] = d;
    }
    __syncthreads();

    int cg   = t & (CG_ - 1);        // channel group 0..63
    int lane = t >> 6;               // cell lane 0..7 (full pool row +1 in flight)

    const char* fbase = (const char*)(s_lvl ? feat1 : feat0) + cg * 16;
    longlong2* outbase = (longlong2*)out + (size_t)n * NCELLB_ * (C_ / 4) + cg;

    #pragma unroll
    for (int i = 0; i < 7; i++) {
        int cell = lane + i * 8;
        Desc d = cd[cell];
        ulonglong2 a = ldg_el(fbase + d.o.x);
        ulonglong2 c = ldg_el(fbase + d.o.y);
        ulonglong2 e = ldg_el(fbase + d.o.z);
        ulonglong2 f = ldg_el(fbase + d.o.w);

        ulonglong2 r;
        r.x = fma2(f.x, d.wB.y, fma2(e.x, d.wB.x, fma2(c.x, d.wA.y, mul2(a.x, d.wA.x))));
        r.y = fma2(f.y, d.wB.y, fma2(e.y, d.wB.x, fma2(c.y, d.wA.y, mul2(a.y, d.wA.x))));

        if (cell < NCELLB_) {
            longlong2 rs;
            rs.x = (long long)r.x;
            rs.y = (long long)r.y;
            __stcs(outbase + cell * (C_ / 4), rs);
        }
    }
}

extern "C" void kernel_launch(void* const* d_in, const int* in_sizes, int n_in,
                              void* d_out, int out_size)
{
    const float* feat0 = (const float*)d_in[0];
    const float* feat1 = (const float*)d_in[1];
    const float* rois  = (const float*)d_in[2];
    float* out = (float*)d_out;

    roialign_kernel<<<NBOX_, THREADS_>>>(feat0, feat1, rois, out);
}